// round 2
// baseline (speedup 1.0000x reference)
#include <cuda_runtime.h>
#include <math.h>

#define NB 128
#define NT 256
#define ROWS 8
#define NN 1024
#define CC 64
#define NITERS 20
#define LSCALE 0.001f

// ---------------- device globals (no cudaMalloc allowed) ----------------
__device__ float g_psT[CC * NN];   // transposed softmax of y_s[7]  [C][N]
__device__ float g_ptT[CC * NN];   // transposed softmax of y_t[7]  [C][N]
__device__ float g_W[NN * NN];
__device__ float g_K[NN * NN];
__device__ float g_u[NN];
__device__ float g_v[NN];
__device__ float g_partial[NB];
__device__ unsigned g_cnt[48];              // zero-init; reset by last arriver
__device__ volatile unsigned g_flag[48];    // monotonic generation counters

// ---------------- reductions ----------------
__device__ __forceinline__ float warp_sum(float v) {
#pragma unroll
    for (int o = 16; o > 0; o >>= 1) v += __shfl_down_sync(0xffffffffu, v, o);
    return v;
}
__device__ __forceinline__ float warp_max(float v) {
#pragma unroll
    for (int o = 16; o > 0; o >>= 1) v = fmaxf(v, __shfl_down_sync(0xffffffffu, v, o));
    return v;
}
__device__ float block_sum(float v, float* sc) {
    int t = threadIdx.x;
    v = warp_sum(v);
    if ((t & 31) == 0) sc[t >> 5] = v;
    __syncthreads();
    if (t == 0) {
        float r = 0.f;
#pragma unroll
        for (int i = 0; i < 8; i++) r += sc[i];
        sc[8] = r;
    }
    __syncthreads();
    float r = sc[8];
    __syncthreads();
    return r;
}
__device__ float block_max(float v, float* sc) {
    int t = threadIdx.x;
    v = warp_max(v);
    if ((t & 31) == 0) sc[t >> 5] = v;
    __syncthreads();
    if (t == 0) {
        float r = -3.4e38f;
#pragma unroll
        for (int i = 0; i < 8; i++) r = fmaxf(r, sc[i]);
        sc[8] = r;
    }
    __syncthreads();
    float r = sc[8];
    __syncthreads();
    return r;
}

// ---------------- software grid barrier ----------------
// Generation-based: g_flag[k] counts completed launches for slot k, so no
// reset race across graph replays. Last arriver zeroes the count and bumps
// the flag; others spin on the (L1-bypassing, volatile) flag.
__device__ __forceinline__ void gbar(int k, unsigned R) {
    __syncthreads();
    if (threadIdx.x == 0) {
        __threadfence();
        unsigned old = atomicAdd(&g_cnt[k], 1u);
        if (old == NB - 1) {
            g_cnt[k] = 0;          // safe: every block already arrived
            __threadfence();
            g_flag[k] = R + 1;
        } else {
            while (g_flag[k] != R + 1) { }
            __threadfence();
        }
    }
    __syncthreads();
}

// ---------------- fused persistent kernel ----------------
__global__ __launch_bounds__(NT) void fused_kernel(const float* __restrict__ ys,
                                                   const float* __restrict__ yt,
                                                   float* __restrict__ out) {
    extern __shared__ float sm[];
    float* sK   = sm;                       // 8*1024
    float* sKT  = sm + ROWS * NN;           // 8*1024
    float* sVec = sm + 2 * ROWS * NN;       // 1024
    float* sPS  = sVec + NN;                // 8*64
    float* sRed = sPS + ROWS * CC;          // 16

    int b = blockIdx.x, t = threadIdx.x;
    unsigned R = 0;
    if (t == 0) R = g_flag[0];   // stable: flags only change after ALL blocks arrive

    // ---- Phase A: softmax over N axis for batch sample 7, one channel/block ----
    {
        const float* y  = (b < CC) ? ys : yt;
        float* pT       = (b < CC) ? g_psT : g_ptT;
        int c = b & (CC - 1);
        const float* base = y + 7 * NN * CC;
        float vals[4];
        float mx = -3.4e38f;
#pragma unroll
        for (int k = 0; k < 4; k++) {
            vals[k] = base[(t + k * NT) * CC + c] * 0.5f;  // y / T, T=2
            mx = fmaxf(mx, vals[k]);
        }
        mx = block_max(mx, sRed);
        float s = 0.f;
#pragma unroll
        for (int k = 0; k < 4; k++) { vals[k] = expf(vals[k] - mx); s += vals[k]; }
        s = block_sum(s, sRed);
        float inv = 1.0f / s;
#pragma unroll
        for (int k = 0; k < 4; k++) pT[c * NN + t + k * NT] = vals[k] * inv;
    }
    gbar(0, R);

    // ---- Phase B: W rows + K rows for this block; K rows stay in smem ----
    int i0 = b * ROWS;
    {
        for (int idx = t; idx < ROWS * CC; idx += NT) {
            int i = idx >> 6, c = idx & 63;
            sPS[idx] = g_psT[c * NN + i0 + i];
        }
        __syncthreads();

        float acc[ROWS][4];
#pragma unroll
        for (int i = 0; i < ROWS; i++)
#pragma unroll
            for (int q = 0; q < 4; q++) acc[i][q] = 0.f;

        int j0 = t * 4;
        for (int c = 0; c < CC; c++) {
            float4 bv = *(const float4*)&g_ptT[c * NN + j0];
#pragma unroll
            for (int i = 0; i < ROWS; i++) {
                float a = sPS[i * CC + c];
                acc[i][0] += fabsf(a - bv.x);
                acc[i][1] += fabsf(a - bv.y);
                acc[i][2] += fabsf(a - bv.z);
                acc[i][3] += fabsf(a - bv.w);
            }
        }
#pragma unroll
        for (int i = 0; i < ROWS; i++) {
            float4 wv = make_float4(acc[i][0], acc[i][1], acc[i][2], acc[i][3]);
            float4 kv = make_float4(__expf(-10.0f * wv.x), __expf(-10.0f * wv.y),
                                    __expf(-10.0f * wv.z), __expf(-10.0f * wv.w));
            *(float4*)&g_W[(size_t)(i0 + i) * NN + j0] = wv;
            *(float4*)&g_K[(size_t)(i0 + i) * NN + j0] = kv;
            *(float4*)&sK[i * NN + j0] = kv;
        }
        if (t < ROWS) g_v[i0 + t] = 1.0f;
    }
    gbar(1, R);

    // ---- gather this block's 8 columns of K as rows of K^T into smem ----
    {
#pragma unroll
        for (int r = 0; r < 4; r++) {
            int i = t * 4 + r;
            float4 x0 = *(const float4*)&g_K[(size_t)i * NN + i0];
            float4 x1 = *(const float4*)&g_K[(size_t)i * NN + i0 + 4];
            sKT[0 * NN + i] = x0.x; sKT[1 * NN + i] = x0.y;
            sKT[2 * NN + i] = x0.z; sKT[3 * NN + i] = x0.w;
            sKT[4 * NN + i] = x1.x; sKT[5 * NN + i] = x1.y;
            sKT[6 * NN + i] = x1.z; sKT[7 * NN + i] = x1.w;
        }
    }
    // (sync before first use provided inside gbar(2+...))

    int w = t >> 5, l = t & 31;

    // ---- Phase C: 20 Sinkhorn iterations, 2 global barriers each ----
    for (int it = 0; it < NITERS; it++) {
        // u = 1 / (K v)
        ((float4*)sVec)[t] = ((const float4*)g_v)[t];
        __syncthreads();
        {
            const float* Kr = sK + w * NN;
            float s = 0.f;
#pragma unroll
            for (int k = 0; k < 8; k++) {
                int j = (l + k * 32) * 4;
                float4 kv = *(const float4*)&Kr[j];
                float4 vv = *(const float4*)&sVec[j];
                s += kv.x * vv.x + kv.y * vv.y + kv.z * vv.z + kv.w * vv.w;
            }
            s = warp_sum(s);
            if (l == 0) g_u[i0 + w] = 1.0f / s;
        }
        gbar(2 + it * 2, R);

        // v = 1 / (K^T u)
        ((float4*)sVec)[t] = ((const float4*)g_u)[t];
        __syncthreads();
        {
            const float* Kr = sKT + w * NN;
            float s = 0.f;
#pragma unroll
            for (int k = 0; k < 8; k++) {
                int j = (l + k * 32) * 4;
                float4 kv = *(const float4*)&Kr[j];
                float4 vv = *(const float4*)&sVec[j];
                s += kv.x * vv.x + kv.y * vv.y + kv.z * vv.z + kv.w * vv.w;
            }
            s = warp_sum(s);
            if (l == 0) g_v[i0 + w] = 1.0f / s;
        }
        gbar(3 + it * 2, R);
    }

    // ---- Phase D: loss = sum u_i K_ij v_j W_ij ----
    ((float4*)sVec)[t] = ((const float4*)g_v)[t];
    __syncthreads();
    {
        float uw = g_u[i0 + w];
        const float* Kr = sK + w * NN;
        const float* Wr = g_W + (size_t)(i0 + w) * NN;
        float s = 0.f;
#pragma unroll
        for (int k = 0; k < 8; k++) {
            int j = (l + k * 32) * 4;
            float4 kv = *(const float4*)&Kr[j];
            float4 wv = *(const float4*)&Wr[j];
            float4 vv = *(const float4*)&sVec[j];
            s += kv.x * wv.x * vv.x + kv.y * wv.y * vv.y
               + kv.z * wv.z * vv.z + kv.w * wv.w * vv.w;
        }
        s = warp_sum(s) * uw;
        if (l == 0) sRed[w] = s;
        __syncthreads();
        if (t == 0) {
            float tot = 0.f;
#pragma unroll
            for (int i = 0; i < 8; i++) tot += sRed[i];
            g_partial[b] = tot;
        }
    }
    gbar(42, R);

    if (b == 0 && t == 0) {
        float tot = 0.f;
        for (int i = 0; i < NB; i++) tot += g_partial[i];
        out[0] = LSCALE * tot;
    }
}

#define SMEM_BYTES ((2 * ROWS * NN + NN + ROWS * CC + 16) * (int)sizeof(float))

extern "C" void kernel_launch(void* const* d_in, const int* in_sizes, int n_in,
                              void* d_out, int out_size) {
    const float* ys = (const float*)d_in[0];
    const float* yt = (const float*)d_in[1];
    cudaFuncSetAttribute(fused_kernel, cudaFuncAttributeMaxDynamicSharedMemorySize,
                         SMEM_BYTES);
    fused_kernel<<<NB, NT, SMEM_BYTES>>>(ys, yt, (float*)d_out);
}

// round 3
// speedup vs baseline: 1.1638x; 1.1638x over previous
#include <cuda_runtime.h>
#include <math.h>

#define NB 128
#define NT 256
#define ROWS 8
#define NN 1024
#define CC 64
#define NITERS 20
#define LSCALE 0.001f

// ---------------- device globals (no cudaMalloc allowed) ----------------
__device__ float g_psT[CC * NN];   // transposed softmax of y_s[7]  [C][N]
__device__ float g_ptT[CC * NN];   // transposed softmax of y_t[7]  [C][N]
__device__ float g_W[NN * NN];
__device__ float g_K[NN * NN];
__device__ float g_u[NN];
__device__ float g_v[NN];
__device__ float g_partial[NB];
__device__ unsigned g_cnt[64];     // zero-init; reset by last arriver each use
__device__ unsigned g_flag[64];    // monotonic generation counters

// ---------------- reductions ----------------
__device__ __forceinline__ float warp_sum(float v) {
#pragma unroll
    for (int o = 16; o > 0; o >>= 1) v += __shfl_down_sync(0xffffffffu, v, o);
    return v;
}
__device__ __forceinline__ float warp_max(float v) {
#pragma unroll
    for (int o = 16; o > 0; o >>= 1) v = fmaxf(v, __shfl_down_sync(0xffffffffu, v, o));
    return v;
}
__device__ float block_sum(float v, float* sc) {
    int t = threadIdx.x;
    v = warp_sum(v);
    if ((t & 31) == 0) sc[t >> 5] = v;
    __syncthreads();
    if (t == 0) {
        float r = 0.f;
#pragma unroll
        for (int i = 0; i < 8; i++) r += sc[i];
        sc[8] = r;
    }
    __syncthreads();
    float r = sc[8];
    __syncthreads();
    return r;
}
__device__ float block_max(float v, float* sc) {
    int t = threadIdx.x;
    v = warp_max(v);
    if ((t & 31) == 0) sc[t >> 5] = v;
    __syncthreads();
    if (t == 0) {
        float r = -3.4e38f;
#pragma unroll
        for (int i = 0; i < 8; i++) r = fmaxf(r, sc[i]);
        sc[8] = r;
    }
    __syncthreads();
    float r = sc[8];
    __syncthreads();
    return r;
}

// ---------------- gpu-scope software grid barrier ----------------
// Generation flags are monotonic across graph replays (no reset race).
// Reading R at kernel start is safe: g_flag[k] only advances after ALL
// blocks arrive at gbar(k), which every block does only after reading R.
// acq_rel RMW chain on the counter + release flag store + acquire polls
// gives gpu-scope visibility of all pre-barrier writes (and the gpu-scope
// acquire invalidates stale L1 lines).
__device__ __forceinline__ void gbar(int k, unsigned R) {
    __syncthreads();
    if (threadIdx.x == 0) {
        unsigned* cnt = &g_cnt[k];
        unsigned* flg = &g_flag[k];
        unsigned old;
        asm volatile("atom.acq_rel.gpu.global.add.u32 %0, [%1], %2;"
                     : "=r"(old) : "l"(cnt), "r"(1u) : "memory");
        if (old == NB - 1) {
            asm volatile("st.relaxed.gpu.global.u32 [%0], %1;"
                         :: "l"(cnt), "r"(0u) : "memory");
            asm volatile("st.release.gpu.global.u32 [%0], %1;"
                         :: "l"(flg), "r"(R + 1) : "memory");
        } else {
            unsigned v;
            do {
                asm volatile("ld.acquire.gpu.global.u32 %0, [%1];"
                             : "=r"(v) : "l"(flg) : "memory");
            } while (v != R + 1);
        }
    }
    __syncthreads();
}

// one Sinkhorn half-step: gout[i0+w] = 1 / (Krows[w,:] . gin)
__device__ __forceinline__ void halfstep(const float* __restrict__ Krows,
                                         const float* __restrict__ gin,
                                         float* __restrict__ gout,
                                         int i0, float* sVec, int t) {
    ((float4*)sVec)[t] = ((const float4*)gin)[t];
    __syncthreads();
    int w = t >> 5, l = t & 31;
    const float* Kr = Krows + w * NN;
    float s = 0.f;
#pragma unroll
    for (int k = 0; k < 8; k++) {
        int j = (l + k * 32) * 4;
        float4 kv = *(const float4*)&Kr[j];
        float4 vv = *(const float4*)&sVec[j];
        s += kv.x * vv.x + kv.y * vv.y + kv.z * vv.z + kv.w * vv.w;
    }
    s = warp_sum(s);
    if (l == 0) gout[i0 + w] = 1.0f / s;
}

// ---------------- fused persistent kernel ----------------
__global__ __launch_bounds__(NT) void fused_kernel(const float* __restrict__ ys,
                                                   const float* __restrict__ yt,
                                                   float* __restrict__ out) {
    extern __shared__ float sm[];
    float* sK   = sm;                       // 8*1024
    float* sKT  = sm + ROWS * NN;           // 8*1024
    float* sVec = sm + 2 * ROWS * NN;       // 1024
    float* sPS  = sVec + NN;                // 8*64
    float* sRed = sPS + ROWS * CC;          // 16

    int b = blockIdx.x, t = threadIdx.x;
    unsigned R = 0;
    if (t == 0)
        asm volatile("ld.relaxed.gpu.global.u32 %0, [%1];"
                     : "=r"(R) : "l"(&g_flag[0]) : "memory");

    // ---- Phase A: softmax over N axis for batch sample 7 (one channel/block)
    {
        const float* y = (b < CC) ? ys : yt;
        float* pT      = (b < CC) ? g_psT : g_ptT;
        int c = b & (CC - 1);
        const float* base = y + 7 * NN * CC;
        float vals[4];
        float mx = -3.4e38f;
#pragma unroll
        for (int k = 0; k < 4; k++) {
            vals[k] = base[(t + k * NT) * CC + c] * 0.5f;   // y / T, T=2
            mx = fmaxf(mx, vals[k]);
        }
        mx = block_max(mx, sRed);
        float s = 0.f;
#pragma unroll
        for (int k = 0; k < 4; k++) { vals[k] = expf(vals[k] - mx); s += vals[k]; }
        s = block_sum(s, sRed);
        float inv = 1.0f / s;
#pragma unroll
        for (int k = 0; k < 4; k++) pT[c * NN + t + k * NT] = vals[k] * inv;
    }
    gbar(0, R);

    // ---- Phase B: W/K rows via packed f32x2 |a-b| accumulation ----
    int i0 = b * ROWS;
    {
        for (int idx = t; idx < ROWS * CC; idx += NT) {
            int i = idx >> 6, c = idx & 63;
            sPS[idx] = g_psT[c * NN + i0 + i];
        }
        __syncthreads();

        const unsigned long long SMASK = 0x8000000080000000ULL;
        const unsigned long long AMASK = 0x7FFFFFFF7FFFFFFFULL;
        unsigned long long acc0[ROWS], acc1[ROWS];
#pragma unroll
        for (int i = 0; i < ROWS; i++) { acc0[i] = 0ULL; acc1[i] = 0ULL; }

        int j0 = t * 4;
        for (int c = 0; c < CC; c++) {
            ulonglong2 bv = *(const ulonglong2*)&g_ptT[c * NN + j0];
            unsigned long long nb0 = bv.x ^ SMASK;   // (-b0, -b1) packed
            unsigned long long nb1 = bv.y ^ SMASK;   // (-b2, -b3) packed
#pragma unroll
            for (int i = 0; i < ROWS; i++) {
                unsigned ai = __float_as_uint(sPS[i * CC + c]);
                unsigned long long aa, d0, d1;
                asm("mov.b64 %0, {%1, %1};" : "=l"(aa) : "r"(ai));
                asm("add.rn.f32x2 %0, %1, %2;" : "=l"(d0) : "l"(aa), "l"(nb0));
                asm("add.rn.f32x2 %0, %1, %2;" : "=l"(d1) : "l"(aa), "l"(nb1));
                d0 &= AMASK;                        // packed fabs
                d1 &= AMASK;
                asm("add.rn.f32x2 %0, %0, %1;" : "+l"(acc0[i]) : "l"(d0));
                asm("add.rn.f32x2 %0, %0, %1;" : "+l"(acc1[i]) : "l"(d1));
            }
        }
#pragma unroll
        for (int i = 0; i < ROWS; i++) {
            unsigned x0, x1, x2, x3;
            asm("mov.b64 {%0, %1}, %2;" : "=r"(x0), "=r"(x1) : "l"(acc0[i]));
            asm("mov.b64 {%0, %1}, %2;" : "=r"(x2), "=r"(x3) : "l"(acc1[i]));
            float4 wv = make_float4(__uint_as_float(x0), __uint_as_float(x1),
                                    __uint_as_float(x2), __uint_as_float(x3));
            float4 kv = make_float4(__expf(-10.0f * wv.x), __expf(-10.0f * wv.y),
                                    __expf(-10.0f * wv.z), __expf(-10.0f * wv.w));
            *(float4*)&g_W[(size_t)(i0 + i) * NN + j0] = wv;
            *(float4*)&g_K[(size_t)(i0 + i) * NN + j0] = kv;
            *(float4*)&sK[i * NN + j0] = kv;
        }
        __syncthreads();

        // first u-step is local: u0 = 1 / rowsum(sK)  (v == 1), no barrier needed
        int w = t >> 5, l = t & 31;
        const float* Kr = sK + w * NN;
        float s = 0.f;
#pragma unroll
        for (int k = 0; k < 8; k++) {
            int j = (l + k * 32) * 4;
            float4 kv = *(const float4*)&Kr[j];
            s += kv.x + kv.y + kv.z + kv.w;
        }
        s = warp_sum(s);
        if (l == 0) g_u[i0 + w] = 1.0f / s;
    }
    gbar(1, R);   // all g_K rows + u0 visible

    // ---- gather this block's 8 columns of K as rows of K^T into smem ----
#pragma unroll
    for (int r = 0; r < 4; r++) {
        int i = t * 4 + r;
        float4 x0 = *(const float4*)&g_K[(size_t)i * NN + i0];
        float4 x1 = *(const float4*)&g_K[(size_t)i * NN + i0 + 4];
        sKT[0 * NN + i] = x0.x; sKT[1 * NN + i] = x0.y;
        sKT[2 * NN + i] = x0.z; sKT[3 * NN + i] = x0.w;
        sKT[4 * NN + i] = x1.x; sKT[5 * NN + i] = x1.y;
        sKT[6 * NN + i] = x1.z; sKT[7 * NN + i] = x1.w;
    }
    // (sync before first use happens inside halfstep)

    // ---- Phase C: remaining Sinkhorn half-steps ----
    int slot = 2;
    for (int it = 0; it < NITERS; it++) {
        halfstep(sKT, g_u, g_v, i0, sVec, t);    // v = 1/(K^T u)
        gbar(slot++, R);
        if (it < NITERS - 1) {
            halfstep(sK, g_v, g_u, i0, sVec, t); // u = 1/(K v)
            gbar(slot++, R);
        }
    }

    // ---- Phase D: loss = sum_ij u_i K_ij v_j W_ij ----
    {
        ((float4*)sVec)[t] = ((const float4*)g_v)[t];
        __syncthreads();
        int w = t >> 5, l = t & 31;
        float uw = g_u[i0 + w];
        const float* Kr = sK + w * NN;
        const float* Wr = g_W + (size_t)(i0 + w) * NN;
        float s = 0.f;
#pragma unroll
        for (int k = 0; k < 8; k++) {
            int j = (l + k * 32) * 4;
            float4 kv = *(const float4*)&Kr[j];
            float4 wv = *(const float4*)&Wr[j];
            float4 vv = *(const float4*)&sVec[j];
            s += kv.x * wv.x * vv.x + kv.y * wv.y * vv.y
               + kv.z * wv.z * vv.z + kv.w * wv.w * vv.w;
        }
        s = warp_sum(s) * uw;
        if (l == 0) sRed[w] = s;
        __syncthreads();
        if (t == 0) {
            float tot = 0.f;
#pragma unroll
            for (int i = 0; i < 8; i++) tot += sRed[i];
            g_partial[b] = tot;
        }
    }
    gbar(slot++, R);

    if (b == 0) {
        float v = (t < NB) ? g_partial[t] : 0.f;
        v = block_sum(v, sRed);
        if (t == 0) out[0] = LSCALE * v;
    }
}

#define SMEM_BYTES ((2 * ROWS * NN + NN + ROWS * CC + 16) * (int)sizeof(float))

extern "C" void kernel_launch(void* const* d_in, const int* in_sizes, int n_in,
                              void* d_out, int out_size) {
    const float* ys = (const float*)d_in[0];
    const float* yt = (const float*)d_in[1];
    cudaFuncSetAttribute(fused_kernel, cudaFuncAttributeMaxDynamicSharedMemorySize,
                         SMEM_BYTES);
    fused_kernel<<<NB, NT, SMEM_BYTES>>>(ys, yt, (float*)d_out);
}